// round 17
// baseline (speedup 1.0000x reference)
#include <cuda_runtime.h>
#include <cstdint>
#include <cstddef>

// Axial attention on a 7x7 grid (N=512, Cq=64, Cv=512).
// out[n,c,h,w] = sum_j p[n,h,w,j]   * vH[(n*7+w), c, j]
//             + sum_y p[n,h,w,7+y] * vW[(n*7+h), c, y]
// p = softmax over 14 of [eH (diag-masked, transposed), eW].
//
// Producer/consumer pipelined via PDL + per-n flags:
//   A: one block per (n, pass), 25KB smem -> 8 blocks/SM, one wave.
//      Each increments g_flag[n]; consumers wait for >= 2.
//   B: PDL-launched, overlaps A; v cp.asyncs issue before the flag spin.
//      Bounce buffer is in OUTPUT layout -> epilogue is a float4 memcpy.

#define NEGV (-1e20f)
#define MAXN 1024

__device__ float    g_lg[(size_t)MAXN * 49 * 14];
__device__ unsigned g_flag[MAXN];

static __device__ __forceinline__ uint32_t s2u(const void* p) {
    return (uint32_t)__cvta_generic_to_shared(p);
}
#define CP_ASYNC16(dst_u32, src_ptr) \
    asm volatile("cp.async.cg.shared.global [%0], [%1], 16;" \
                 :: "r"(dst_u32), "l"(src_ptr))
#define CP_COMMIT()  asm volatile("cp.async.commit_group;")
#define CP_WAIT0()   asm volatile("cp.async.wait_group 0;")

// ---------------------------------------------------------------------------
// Kernel A: raw logits. Block = (n, pass), 384 threads, 25.3KB static smem.
// ---------------------------------------------------------------------------
#define SL  452
#define TSL (7 * SL)

__global__ __launch_bounds__(384) void ax_logits(
    const float* __restrict__ qH, const float* __restrict__ kH,
    const float* __restrict__ qW, const float* __restrict__ kW)
{
    __shared__ float sm[2 * TSL];

    asm volatile("griddepcontrol.launch_dependents;" ::: "memory");

    const int n    = blockIdx.x;
    const int pass = blockIdx.y;
    const int tid  = threadIdx.x;

    {
        const float4* q4 = (const float4*)((pass ? qW : qH) + (size_t)n * 3136);
        const float4* k4 = (const float4*)((pass ? kW : kH) + (size_t)n * 3136);
        for (int i = tid; i < 784; i += 384) {
            int a = i / 112, r = i - a * 112;
            ((float4*)sm)[a * 113 + r]         = q4[i];
            ((float4*)(sm + TSL))[a * 113 + r] = k4[i];
        }
    }
    __syncthreads();

    if (tid < 343) {
        const int h = tid / 49, rem = tid % 49, w = rem / 7, j = rem % 7;
        const int a   = pass ? h : w;
        const int row = pass ? w : h;
        const float* qp = sm + a * SL + row * 64;
        const float* kp = sm + TSL + a * SL + j;
        float s = 0.f;
        #pragma unroll
        for (int c = 0; c < 64; c += 4) {
            float4 x = *(const float4*)(qp + c);
            s += x.x * kp[c * 7]       + x.y * kp[(c + 1) * 7]
               + x.z * kp[(c + 2) * 7] + x.w * kp[(c + 3) * 7];
        }
        if (pass == 0 && h == j) s = NEGV;
        g_lg[(size_t)n * 686 + (size_t)(h * 7 + w) * 14 + pass * 7 + j] = s;
    }
    __syncthreads();

    if (tid == 0) {
        __threadfence();
        asm volatile("red.release.gpu.global.add.u32 [%0], 1;"
                     :: "l"(&g_flag[n]) : "memory");
    }
}

// ---------------------------------------------------------------------------
// Kernel B: softmax + PV. Block = (c-chunk of 128, n), 256 threads.
// Thread = (c1 = tid&63, c2 = c1+64, q = tid>>6 -> h-quarter). Bounce buffer
// is laid out EXACTLY like the output block [c][hw] (stride-49 STS: 49%32=17,
// conflict-free), so the global store is a contiguous float4 copy.
// ---------------------------------------------------------------------------
#define CHUNK  128
#define PH_OFF 0
#define PW_OFF 392
#define VH_OFF 784
#define VW_OFF 7056
#define BN_OFF 784                   // bounce aliases vh exactly (6272 floats)
#define SMEMB_FLOATS 13328
#define SMEMB_BYTES (SMEMB_FLOATS * 4)

template<int HBASE, int NH>
static __device__ __forceinline__ void pv_compute2(
    const float* __restrict__ sm, int c1, int c2,
    float acc1[NH][7], float acc2[NH][7])
{
    const float* pHs = sm + PH_OFF;
    const float* pWs = sm + PW_OFF;

    #pragma unroll
    for (int w = 0; w < 7; w++) {
        const float* va = sm + VH_OFF + w * 896 + c1 * 7;
        const float* vb = sm + VH_OFF + w * 896 + c2 * 7;
        float a0 = va[0], a1 = va[1], a2 = va[2], a3 = va[3],
              a4 = va[4], a5 = va[5], a6 = va[6];
        float b0 = vb[0], b1 = vb[1], b2 = vb[2], b3 = vb[3],
              b4 = vb[4], b5 = vb[5], b6 = vb[6];
        #pragma unroll
        for (int hh = 0; hh < NH; hh++) {
            const int h = HBASE + hh;
            const float4 p0 = *(const float4*)(pHs + (h * 7 + w) * 8);
            const float4 p1 = *(const float4*)(pHs + (h * 7 + w) * 8 + 4);
            acc1[hh][w] = p0.x * a0 + p0.y * a1 + p0.z * a2 + p0.w * a3
                        + p1.x * a4 + p1.y * a5 + p1.z * a6;
            acc2[hh][w] = p0.x * b0 + p0.y * b1 + p0.z * b2 + p0.w * b3
                        + p1.x * b4 + p1.y * b5 + p1.z * b6;
        }
    }
    #pragma unroll
    for (int hh = 0; hh < NH; hh++) {
        const int h = HBASE + hh;
        const float* va = sm + VW_OFF + h * 896 + c1 * 7;
        const float* vb = sm + VW_OFF + h * 896 + c2 * 7;
        float a0 = va[0], a1 = va[1], a2 = va[2], a3 = va[3],
              a4 = va[4], a5 = va[5], a6 = va[6];
        float b0 = vb[0], b1 = vb[1], b2 = vb[2], b3 = vb[3],
              b4 = vb[4], b5 = vb[5], b6 = vb[6];
        #pragma unroll
        for (int w = 0; w < 7; w++) {
            const float4 p0 = *(const float4*)(pWs + (h * 7 + w) * 8);
            const float4 p1 = *(const float4*)(pWs + (h * 7 + w) * 8 + 4);
            acc1[hh][w] += p0.x * a0 + p0.y * a1 + p0.z * a2 + p0.w * a3
                         + p1.x * a4 + p1.y * a5 + p1.z * a6;
            acc2[hh][w] += p0.x * b0 + p0.y * b1 + p0.z * b2 + p0.w * b3
                         + p1.x * b4 + p1.y * b5 + p1.z * b6;
        }
    }
}

template<int HBASE, int NH>
static __device__ __forceinline__ void pv_store2(
    float* __restrict__ bnc, int c1, int c2,
    const float acc1[NH][7], const float acc2[NH][7])
{
    // Output layout: bnc[c * 49 + h*7 + w]. Lanes (consecutive c) are 49
    // floats apart: 49 % 32 = 17, gcd(17,32)=1 -> conflict-free scalar STS.
    #pragma unroll
    for (int hh = 0; hh < NH; hh++)
        #pragma unroll
        for (int w = 0; w < 7; w++) {
            const int hw = (HBASE + hh) * 7 + w;
            bnc[c1 * 49 + hw] = acc1[hh][w];
            bnc[c2 * 49 + hw] = acc2[hh][w];
        }
}

__global__ __launch_bounds__(256, 4) void ax_pv(
    const float* __restrict__ vH, const float* __restrict__ vW,
    float* __restrict__ out, int Cv)
{
    extern __shared__ float sm[];
    float* pHs = sm + PH_OFF;
    float* pWs = sm + PW_OFF;

    const int n   = blockIdx.y;
    const int c0  = blockIdx.x * CHUNK;
    const int tid = threadIdx.x;
    const int c1  = tid & 63;
    const int c2  = c1 + 64;
    const int q   = tid >> 6;

    const size_t bstr = (size_t)Cv * 7;
    const uint32_t smb = s2u(sm);

    // ---- issue ALL v cp.asyncs (independent of producer) ----
    {
        const float* bh = vH + (size_t)n * 7 * bstr + (size_t)c0 * 7;
        const float* bw = vW + (size_t)n * 7 * bstr + (size_t)c0 * 7;
        for (int i = tid; i < 1568; i += 256) {
            int w = i / 224, r = i - w * 224;
            CP_ASYNC16(smb + (VH_OFF + w * 896 + r * 4) * 4,
                       bh + w * bstr + r * 4);
            CP_ASYNC16(smb + (VW_OFF + w * 896 + r * 4) * 4,
                       bw + w * bstr + r * 4);
        }
        CP_COMMIT();
    }

    // ---- per-n dependency: both producer passes must have released ----
    if (tid == 0) {
        unsigned v;
        while (true) {
            asm volatile("ld.acquire.gpu.global.u32 %0, [%1];"
                         : "=r"(v) : "l"(&g_flag[n]) : "memory");
            if (v >= 2u) break;
            __nanosleep(64);
        }
    }
    __syncthreads();

    // ---- softmax over 14 (direct L2 reads of just-written logits) ----
    if (tid < 49) {
        const float* row = g_lg + (size_t)n * 686 + tid * 14;
        float l[14];
        #pragma unroll
        for (int s = 0; s < 14; s++) l[s] = row[s];
        float m = l[0];
        #pragma unroll
        for (int s = 1; s < 14; s++) m = fmaxf(m, l[s]);
        float e[14];
        float sum = 0.f;
        #pragma unroll
        for (int s = 0; s < 14; s++) { e[s] = __expf(l[s] - m); sum += e[s]; }
        const float inv = 1.f / sum;
        #pragma unroll
        for (int s = 0; s < 7; s++) {
            pHs[tid * 8 + s] = e[s]     * inv;
            pWs[tid * 8 + s] = e[s + 7] * inv;
        }
        pHs[tid * 8 + 7] = 0.f;
        pWs[tid * 8 + 7] = 0.f;
    }

    CP_WAIT0();
    __syncthreads();

    float* bnc = sm + BN_OFF;

    if (q == 0) {
        float acc1[2][7], acc2[2][7];
        pv_compute2<0, 2>(sm, c1, c2, acc1, acc2);
        __syncthreads();
        pv_store2<0, 2>(bnc, c1, c2, acc1, acc2);
    } else if (q == 1) {
        float acc1[2][7], acc2[2][7];
        pv_compute2<2, 2>(sm, c1, c2, acc1, acc2);
        __syncthreads();
        pv_store2<2, 2>(bnc, c1, c2, acc1, acc2);
    } else if (q == 2) {
        float acc1[2][7], acc2[2][7];
        pv_compute2<4, 2>(sm, c1, c2, acc1, acc2);
        __syncthreads();
        pv_store2<4, 2>(bnc, c1, c2, acc1, acc2);
    } else {
        float acc1[1][7], acc2[1][7];
        pv_compute2<6, 1>(sm, c1, c2, acc1, acc2);
        __syncthreads();
        pv_store2<6, 1>(bnc, c1, c2, acc1, acc2);
    }
    __syncthreads();

    // ---- epilogue: bounce is output-layout -> contiguous float4 copy ----
    {
        float4* ob4 = (float4*)(out + ((size_t)n * Cv + c0) * 49);
        const float4* b4 = (const float4*)bnc;
        #pragma unroll 2
        for (int i = tid; i < 1568; i += 256) ob4[i] = b4[i];
    }
}

extern "C" void kernel_launch(void* const* d_in, const int* in_sizes, int n_in,
                              void* d_out, int out_size)
{
    const float* qH = (const float*)d_in[0];
    const float* kH = (const float*)d_in[1];
    const float* vH = (const float*)d_in[2];
    const float* qW = (const float*)d_in[3];
    const float* kW = (const float*)d_in[4];
    const float* vW = (const float*)d_in[5];

    int N  = in_sizes[0] / (49 * 64);
    int Cv = in_sizes[2] / (N * 49);

    static void* flag_addr = nullptr;
    if (!flag_addr) {
        cudaFuncSetAttribute(ax_pv,
                             cudaFuncAttributeMaxDynamicSharedMemorySize,
                             SMEMB_BYTES);
        cudaGetSymbolAddress(&flag_addr, g_flag);
    }

    // Deterministic flag reset (graph-legal memset node).
    cudaMemsetAsync(flag_addr, 0, (size_t)N * sizeof(unsigned), 0);

    // Kernel A: normal launch, one block per (n, pass).
    dim3 ga(N, 2);
    ax_logits<<<ga, 384>>>(qH, kH, qW, kW);

    // Kernel B: programmatic dependent launch; correctness gated by flags.
    {
        cudaLaunchConfig_t cfg = {};
        cfg.gridDim  = dim3((unsigned)((Cv + CHUNK - 1) / CHUNK), (unsigned)N);
        cfg.blockDim = dim3(256);
        cfg.dynamicSmemBytes = SMEMB_BYTES;
        cfg.stream = 0;
        cudaLaunchAttribute attr[1];
        attr[0].id = cudaLaunchAttributeProgrammaticStreamSerialization;
        attr[0].val.programmaticStreamSerializationAllowed = 1;
        cfg.attrs = attr;
        cfg.numAttrs = 1;
        cudaLaunchKernelEx(&cfg, ax_pv, vH, vW, (float*)d_out, Cv);
    }
}